// round 12
// baseline (speedup 1.0000x reference)
#include <cuda_runtime.h>
#include <math.h>

#define TBL 1024
#define THREADS 256
#define CHUNK 8          // patches per thread, loads issued up-front (MLP=8)
#define PER_BLOCK (THREADS * CHUNK)   // 2048 patches per block

// Table of the scalar chain F(s), s in [0,1]:  entry i = { F(i/TBL), F((i+1)/TBL)-F(i/TBL) }
__device__ float2 d_tab[TBL];

// ---------------- Kernel 1: tabulate F(s) with accurate tanhf (single block) ----------------
__device__ __forceinline__ float eval_chain(float s,
                                            const float* __restrict__ Wl,
                                            const float* __restrict__ bl,
                                            const float* __restrict__ scale,
                                            const float* __restrict__ shift,
                                            const float* __restrict__ Wf,
                                            const float* __restrict__ bf)
{
    float x0 = s, x1 = 0.0f;
#pragma unroll
    for (int l = 0; l < 5; l++) {
        float y0 = tanhf(fmaf(x0, __ldg(Wl + 4 * l + 0), fmaf(x1, __ldg(Wl + 4 * l + 1), __ldg(bl + 2 * l + 0))));
        float y1 = tanhf(fmaf(x0, __ldg(Wl + 4 * l + 2), fmaf(x1, __ldg(Wl + 4 * l + 3), __ldg(bl + 2 * l + 1))));
        x0 = fmaf(y0, __ldg(scale + 2 * l + 0), __ldg(shift + 2 * l + 0));
        x1 = fmaf(y1, __ldg(scale + 2 * l + 1), __ldg(shift + 2 * l + 1));
    }
    return fmaf(x0, __ldg(Wf + 0), fmaf(x1, __ldg(Wf + 1), __ldg(bf)));
}

__global__ __launch_bounds__(TBL)
void tab_kernel(const float* __restrict__ Wl, const float* __restrict__ bl,
                const float* __restrict__ scale, const float* __restrict__ shift,
                const float* __restrict__ Wf, const float* __restrict__ bf)
{
    __shared__ float vals[TBL + 1];
    const int j = threadIdx.x;
    const float inv = 1.0f / (float)TBL;
    vals[j] = eval_chain((float)j * inv, Wl, bl, scale, shift, Wf, bf);
    if (j == 0) vals[TBL] = eval_chain(1.0f, Wl, bl, scale, shift, Wf, bf);
    __syncthreads();
    d_tab[j] = make_float2(vals[j], vals[j + 1] - vals[j]);
}

// ---------------- Kernel 2: streaming conv + sigmoid + table lerp (PDL consumer) ----------------
__global__ __launch_bounds__(THREADS)
void fraud_kernel(const float4* __restrict__ data,
                  const float* __restrict__ Wc, const float* __restrict__ bc,
                  float* __restrict__ out, int B)
{
    __shared__ float2 tab[TBL];   // 8 KB

    const int base = blockIdx.x * PER_BLOCK + threadIdx.x;

    // 1) Issue streaming loads FIRST — these don't depend on d_tab, so under PDL
    //    they start while tab_kernel is still running.
    float4 d[CHUNK];
#pragma unroll
    for (int k = 0; k < CHUNK; k++) {
        const int i = base + k * THREADS;
        if (i < B) d[k] = __ldcs(data + i);   // 8 independent LDG.128 -> MLP=8
    }

    // fold -log2(e) into conv weights:  s = 1/(1 + 2^(z'))
    const float NL2E = -1.4426950408889634f;
    const float wc0 = __ldg(Wc + 0) * NL2E, wc1 = __ldg(Wc + 1) * NL2E;
    const float wc2 = __ldg(Wc + 2) * NL2E, wc3 = __ldg(Wc + 3) * NL2E;
    const float bcv = __ldg(bc) * NL2E;

    // 2) Wait for tab_kernel's writes to be visible, THEN preload the table.
    cudaGridDependencySynchronize();

    {
        const float4* src = (const float4*)d_tab;
        float4* dst = (float4*)tab;
#pragma unroll
        for (int i = threadIdx.x; i < TBL / 2; i += THREADS) dst[i] = src[i];
    }

    __syncthreads();

    // 3) consume: conv + sigmoid + table lerp; default write-back stores (L2-resident output)
#pragma unroll
    for (int k = 0; k < CHUNK; k++) {
        const int i = base + k * THREADS;
        if (i >= B) continue;

        const float zp = fmaf(d[k].x, wc0, fmaf(d[k].y, wc1,
                         fmaf(d[k].z, wc2, fmaf(d[k].w, wc3, bcv))));
        float e;
        asm("ex2.approx.f32 %0, %1;" : "=f"(e) : "f"(zp));
        float s;
        asm("rcp.approx.f32 %0, %1;" : "=f"(s) : "f"(e + 1.0f));

        float t = s * (float)TBL;            // t in [0, TBL]
        int idx = (int)t;
        idx = min(idx, TBL - 1);
        const float f = t - (float)idx;
        const float2 v = tab[idx];
        out[i] = fmaf(v.y, f, v.x);
    }
}

extern "C" void kernel_launch(void* const* d_in, const int* in_sizes, int n_in,
                              void* d_out, int out_size)
{
    const float4* data  = (const float4*)d_in[0];
    const float*  Wc    = (const float*)d_in[1];
    const float*  bc    = (const float*)d_in[2];
    const float*  Wl    = (const float*)d_in[3];
    const float*  bl    = (const float*)d_in[4];
    const float*  scale = (const float*)d_in[5];
    const float*  shift = (const float*)d_in[6];
    const float*  Wf    = (const float*)d_in[7];
    const float*  bf    = (const float*)d_in[8];
    float* out = (float*)d_out;

    const int B = in_sizes[0] / 4;          // 4 floats per patch

    tab_kernel<<<1, TBL>>>(Wl, bl, scale, shift, Wf, bf);

    int blocks = (B + PER_BLOCK - 1) / PER_BLOCK;
    if (blocks < 1) blocks = 1;

    // Launch fraud_kernel with programmatic dependent launch so it overlaps
    // tab_kernel; correctness is enforced by cudaGridDependencySynchronize().
    cudaLaunchConfig_t cfg = {};
    cfg.gridDim  = dim3((unsigned)blocks, 1, 1);
    cfg.blockDim = dim3(THREADS, 1, 1);
    cfg.dynamicSmemBytes = 0;
    cfg.stream = 0;
    cudaLaunchAttribute attrs[1];
    attrs[0].id = cudaLaunchAttributeProgrammaticStreamSerialization;
    attrs[0].val.programmaticStreamSerializationAllowed = 1;
    cfg.attrs = attrs;
    cfg.numAttrs = 1;

    cudaLaunchKernelEx(&cfg, fraud_kernel, data, Wc, bc, out, B);
}

// round 13
// speedup vs baseline: 1.1361x; 1.1361x over previous
#include <cuda_runtime.h>
#include <math.h>

#define TBL 1024
#define THREADS 256
#define CHUNK 8          // patches per thread, loads issued up-front (MLP=8)
#define PER_BLOCK (THREADS * CHUNK)   // 2048 patches per block

// Table of the scalar chain F(s), s in [0,1]:  entry i = { F(i/TBL), F((i+1)/TBL)-F(i/TBL) }
__device__ float2 d_tab[TBL];

// tanh via ex2 + rcp:  tanh(y) = 1 - 2/(exp(2y)+1).  abs err ~1e-7, saturates correctly.
// Whole-chain use of this validated at rel_err 6.4e-8 (R2).
__device__ __forceinline__ float fast_tanh(float y) {
    float e;
    asm("ex2.approx.f32 %0, %1;" : "=f"(e) : "f"(y * 2.8853900817779268f)); // 2*log2(e)
    float r;
    asm("rcp.approx.f32 %0, %1;" : "=f"(r) : "f"(e + 1.0f));
    return fmaf(-2.0f, r, 1.0f);
}

// ---------------- Kernel 1: tabulate F(s) ----------------
__device__ __forceinline__ float eval_chain(float s,
                                            const float* __restrict__ Wl,
                                            const float* __restrict__ bl,
                                            const float* __restrict__ scale,
                                            const float* __restrict__ shift,
                                            const float* __restrict__ Wf,
                                            const float* __restrict__ bf)
{
    float x0 = s, x1 = 0.0f;
#pragma unroll
    for (int l = 0; l < 5; l++) {
        float y0 = fast_tanh(fmaf(x0, __ldg(Wl + 4 * l + 0), fmaf(x1, __ldg(Wl + 4 * l + 1), __ldg(bl + 2 * l + 0))));
        float y1 = fast_tanh(fmaf(x0, __ldg(Wl + 4 * l + 2), fmaf(x1, __ldg(Wl + 4 * l + 3), __ldg(bl + 2 * l + 1))));
        x0 = fmaf(y0, __ldg(scale + 2 * l + 0), __ldg(shift + 2 * l + 0));
        x1 = fmaf(y1, __ldg(scale + 2 * l + 1), __ldg(shift + 2 * l + 1));
    }
    return fmaf(x0, __ldg(Wf + 0), fmaf(x1, __ldg(Wf + 1), __ldg(bf)));
}

__global__ void tab_kernel(const float* __restrict__ Wl, const float* __restrict__ bl,
                           const float* __restrict__ scale, const float* __restrict__ shift,
                           const float* __restrict__ Wf, const float* __restrict__ bf)
{
    int j = blockIdx.x * blockDim.x + threadIdx.x;
    if (j >= TBL) return;
    const float inv = 1.0f / (float)TBL;
    float v0 = eval_chain((float)j * inv,       Wl, bl, scale, shift, Wf, bf);
    float v1 = eval_chain((float)(j + 1) * inv, Wl, bl, scale, shift, Wf, bf);
    d_tab[j] = make_float2(v0, v1 - v0);
}

// ---------------- Kernel 2: streaming conv + sigmoid + table lerp ----------------
__global__ __launch_bounds__(THREADS)
void fraud_kernel(const float4* __restrict__ data,
                  const float* __restrict__ Wc, const float* __restrict__ bc,
                  float* __restrict__ out, int B)
{
    __shared__ float2 tab[TBL];   // 8 KB

    const int base = blockIdx.x * PER_BLOCK + threadIdx.x;

    // Issue streaming data loads FIRST so DRAM traffic starts immediately;
    // the table preload + sync then overlaps with their latency.
    float4 d[CHUNK];
#pragma unroll
    for (int k = 0; k < CHUNK; k++) {
        const int i = base + k * THREADS;
        if (i < B) d[k] = __ldcs(data + i);   // 8 independent LDG.128 -> MLP=8, evict-first
    }

    // cooperative table load (8KB: 2 float4 per thread, L2-hot after first wave)
    {
        const float4* src = (const float4*)d_tab;
        float4* dst = (float4*)tab;
#pragma unroll
        for (int i = threadIdx.x; i < TBL / 2; i += THREADS) dst[i] = src[i];
    }

    // fold -log2(e) into conv weights:  s = 1/(1 + 2^(z'))  with z' = -log2(e)*(conv+bias)
    const float NL2E = -1.4426950408889634f;
    const float wc0 = __ldg(Wc + 0) * NL2E, wc1 = __ldg(Wc + 1) * NL2E;
    const float wc2 = __ldg(Wc + 2) * NL2E, wc3 = __ldg(Wc + 3) * NL2E;
    const float bcv = __ldg(bc) * NL2E;

    __syncthreads();

#pragma unroll
    for (int k = 0; k < CHUNK; k++) {
        const int i = base + k * THREADS;
        if (i >= B) continue;

        const float zp = fmaf(d[k].x, wc0, fmaf(d[k].y, wc1,
                         fmaf(d[k].z, wc2, fmaf(d[k].w, wc3, bcv))));
        float e;
        asm("ex2.approx.f32 %0, %1;" : "=f"(e) : "f"(zp));
        float s;
        asm("rcp.approx.f32 %0, %1;" : "=f"(s) : "f"(e + 1.0f));

        float t = s * (float)TBL;            // t in [0, TBL]
        int idx = (int)t;
        idx = min(idx, TBL - 1);
        const float f = t - (float)idx;
        const float2 v = tab[idx];
        // default write-back store: output stays dirty in the 126MB L2 (R11 win)
        out[i] = fmaf(v.y, f, v.x);
    }
}

extern "C" void kernel_launch(void* const* d_in, const int* in_sizes, int n_in,
                              void* d_out, int out_size)
{
    const float4* data  = (const float4*)d_in[0];
    const float*  Wc    = (const float*)d_in[1];
    const float*  bc    = (const float*)d_in[2];
    const float*  Wl    = (const float*)d_in[3];
    const float*  bl    = (const float*)d_in[4];
    const float*  scale = (const float*)d_in[5];
    const float*  shift = (const float*)d_in[6];
    const float*  Wf    = (const float*)d_in[7];
    const float*  bf    = (const float*)d_in[8];
    float* out = (float*)d_out;

    const int B = in_sizes[0] / 4;          // 4 floats per patch

    tab_kernel<<<TBL / 128, 128>>>(Wl, bl, scale, shift, Wf, bf);

    int blocks = (B + PER_BLOCK - 1) / PER_BLOCK;
    if (blocks < 1) blocks = 1;
    fraud_kernel<<<blocks, THREADS>>>(data, Wc, bc, out, B);
}